// round 4
// baseline (speedup 1.0000x reference)
#include <cuda_runtime.h>
#include <stdint.h>

// ---------------------------------------------------------------------------
// Winograd F(2,3) valid conv:
//   x (32,128,64,64) f32, w (256,128,3,3), bias (256) -> out (32,256,62,62)
// Staged pipeline:
//   1) filt_xform : U[p][k][c]       = G g G^T           (2 MB)
//   2) in_xform   : V[p][c][t]       = B^T d B           (253 MB)
//   3) wino_gemm  : M[p][k][t]       = sum_c U*V  (16 independent SGEMMs)
//   4) out_xform  : Y = A^T M A + bias, scatter to NCHW output
// Tile index t = b*961 + pp*31 + qq, NT = 30752, padded to NTP = 241*128.
// ---------------------------------------------------------------------------

#define Bn 32
#define Cc 128
#define Hh 64
#define Ww 64
#define Kk 256
#define TH 31
#define TW 31
#define NT (Bn * TH * TW)     /* 30752 */
#define NTP 30848             /* 241 * 128, padded tile count */
#define OH 62
#define OW 62

// Scratch (static device globals; no runtime allocation).
__device__ float g_U[16 * Kk * Cc];     //  2.1 MB   [p][k][c]
__device__ float g_V[16 * Cc * NTP];    //  253 MB   [p][c][t]
__device__ float g_M[16 * Kk * NTP];    //  505 MB   [p][k][t]

// ---------------------------------------------------------------------------
// 1) Filter transform: U = G g G^T, G = [[1,0,0],[.5,.5,.5],[.5,-.5,.5],[0,0,1]]
//    one thread per (k,c); 32768 threads.
// ---------------------------------------------------------------------------
__global__ void filt_xform(const float* __restrict__ w)
{
    int idx = blockIdx.x * blockDim.x + threadIdx.x;   // 0 .. 32767
    int k = idx >> 7;
    int c = idx & 127;
    const float* g = w + (size_t)(k * Cc + c) * 9;

    float w00 = g[0], w01 = g[1], w02 = g[2];
    float w10 = g[3], w11 = g[4], w12 = g[5];
    float w20 = g[6], w21 = g[7], w22 = g[8];

    // t[a][j] = sum_i G[a][i] * w[i][j]
    float t[4][3];
    t[0][0] = w00;                         t[0][1] = w01;                         t[0][2] = w02;
    t[1][0] = 0.5f * (w00 + w10 + w20);    t[1][1] = 0.5f * (w01 + w11 + w21);    t[1][2] = 0.5f * (w02 + w12 + w22);
    t[2][0] = 0.5f * (w00 - w10 + w20);    t[2][1] = 0.5f * (w01 - w11 + w21);    t[2][2] = 0.5f * (w02 - w12 + w22);
    t[3][0] = w20;                         t[3][1] = w21;                         t[3][2] = w22;

    #pragma unroll
    for (int a = 0; a < 4; a++) {
        float u0 = t[a][0];
        float u1 = 0.5f * (t[a][0] + t[a][1] + t[a][2]);
        float u2 = 0.5f * (t[a][0] - t[a][1] + t[a][2]);
        float u3 = t[a][2];
        g_U[((size_t)(a * 4 + 0) * Kk + k) * Cc + c] = u0;
        g_U[((size_t)(a * 4 + 1) * Kk + k) * Cc + c] = u1;
        g_U[((size_t)(a * 4 + 2) * Kk + k) * Cc + c] = u2;
        g_U[((size_t)(a * 4 + 3) * Kk + k) * Cc + c] = u3;
    }
}

// ---------------------------------------------------------------------------
// 2) Input transform: V = B^T d B, one thread per (c, t); C*NT threads.
//    B^T = [[1,0,-1,0],[0,1,1,0],[0,-1,1,0],[0,1,0,-1]]
// ---------------------------------------------------------------------------
__global__ void in_xform(const float* __restrict__ x)
{
    unsigned idx = blockIdx.x * blockDim.x + threadIdx.x;   // < Cc*NT (exact)
    unsigned c = idx / NT;
    unsigned t = idx - c * NT;
    unsigned b  = t / 961u;
    unsigned r  = t - b * 961u;
    unsigned pp = r / 31u;
    unsigned qq = r - pp * 31u;

    const float* xp = x + (((size_t)(b * Cc + c) * Hh + 2u * pp) * Ww + 2u * qq);

    float d[4][4];
    #pragma unroll
    for (int i = 0; i < 4; i++) {
        #pragma unroll
        for (int j = 0; j < 4; j++)
            d[i][j] = xp[i * Ww + j];
    }

    // tm[a][j] = sum_i Bt[a][i] d[i][j]
    float tm[4][4];
    #pragma unroll
    for (int j = 0; j < 4; j++) {
        tm[0][j] = d[0][j] - d[2][j];
        tm[1][j] = d[1][j] + d[2][j];
        tm[2][j] = d[2][j] - d[1][j];
        tm[3][j] = d[1][j] - d[3][j];
    }

    #pragma unroll
    for (int a = 0; a < 4; a++) {
        float v0 = tm[a][0] - tm[a][2];
        float v1 = tm[a][1] + tm[a][2];
        float v2 = tm[a][2] - tm[a][1];
        float v3 = tm[a][1] - tm[a][3];
        g_V[((size_t)(a * 4 + 0) * Cc + c) * NTP + t] = v0;
        g_V[((size_t)(a * 4 + 1) * Cc + c) * NTP + t] = v1;
        g_V[((size_t)(a * 4 + 2) * Cc + c) * NTP + t] = v2;
        g_V[((size_t)(a * 4 + 3) * Cc + c) * NTP + t] = v3;
    }
}

// ---------------------------------------------------------------------------
// 3) GEMM per winograd point p: M[k][t] = sum_c U[k][c] * V[c][t]
//    CTA tile 128k x 128t, 256 threads, 8x8 microtile, K-chunk = 8.
//    grid = (241 tblocks, 2 kblocks, 16 points)
// ---------------------------------------------------------------------------
__global__ void __launch_bounds__(256, 2) wino_gemm()
{
    __shared__ alignas(16) float As[8][132];   // [c][k], padded row (+4) vs banks
    __shared__ alignas(16) float Vs[8][132];   // [c][t]

    const int p  = blockIdx.z;
    const int kb = blockIdx.y;
    const int tb = blockIdx.x;

    const float* Up = g_U + ((size_t)p * Kk + kb * 128) * Cc;      // [128k][128c]
    const float* Vp = g_V + (size_t)p * Cc * NTP + (size_t)tb * 128;

    const int tid = threadIdx.x;
    const int lk = tid >> 1;            // 0..127  (U loader: row k)
    const int cp = (tid & 1) * 4;       // 0 or 4  (U loader: c sub-offset)
    const int cv = tid >> 5;            // 0..7    (V loader: row c)
    const int tv = (tid & 31) * 4;      // 0..124  (V loader: t offset)
    const int k0 = (tid >> 4) * 8;      // microtile k origin
    const int t0 = (tid & 15) * 8;      // microtile t origin

    float acc[8][8];
    #pragma unroll
    for (int i = 0; i < 8; i++)
        #pragma unroll
        for (int j = 0; j < 8; j++)
            acc[i][j] = 0.0f;

    for (int c0 = 0; c0 < Cc; c0 += 8) {
        float4 ua = *(const float4*)(Up + (size_t)lk * Cc + c0 + cp);
        float4 va = *(const float4*)(Vp + (size_t)(c0 + cv) * NTP + tv);
        __syncthreads();
        As[cp + 0][lk] = ua.x;
        As[cp + 1][lk] = ua.y;
        As[cp + 2][lk] = ua.z;
        As[cp + 3][lk] = ua.w;
        *(float4*)&Vs[cv][tv] = va;
        __syncthreads();

        #pragma unroll
        for (int cc = 0; cc < 8; cc++) {
            float4 a0 = *(const float4*)&As[cc][k0];
            float4 a1 = *(const float4*)&As[cc][k0 + 4];
            float4 b0 = *(const float4*)&Vs[cc][t0];
            float4 b1 = *(const float4*)&Vs[cc][t0 + 4];
            float a[8] = {a0.x, a0.y, a0.z, a0.w, a1.x, a1.y, a1.z, a1.w};
            float bvals[8] = {b0.x, b0.y, b0.z, b0.w, b1.x, b1.y, b1.z, b1.w};
            #pragma unroll
            for (int i = 0; i < 8; i++)
                #pragma unroll
                for (int j = 0; j < 8; j++)
                    acc[i][j] = fmaf(a[i], bvals[j], acc[i][j]);
        }
    }

    float* Mp = g_M + ((size_t)p * Kk + kb * 128 + k0) * NTP + (size_t)tb * 128 + t0;
    #pragma unroll
    for (int i = 0; i < 8; i++) {
        *(float4*)(Mp + (size_t)i * NTP)     = make_float4(acc[i][0], acc[i][1], acc[i][2], acc[i][3]);
        *(float4*)(Mp + (size_t)i * NTP + 4) = make_float4(acc[i][4], acc[i][5], acc[i][6], acc[i][7]);
    }
}

// ---------------------------------------------------------------------------
// 4) Inverse transform + bias: Y = A^T M A, A^T = [[1,1,1,0],[0,1,-1,-1]]
//    one thread per (k, t); K*NT threads.
// ---------------------------------------------------------------------------
__global__ void out_xform(const float* __restrict__ bias, float* __restrict__ out)
{
    unsigned idx = blockIdx.x * blockDim.x + threadIdx.x;   // < Kk*NT (exact)
    unsigned k = idx / NT;
    unsigned t = idx - k * NT;
    unsigned b  = t / 961u;
    unsigned r  = t - b * 961u;
    unsigned pp = r / 31u;
    unsigned qq = r - pp * 31u;

    float m[16];
    #pragma unroll
    for (int p = 0; p < 16; p++)
        m[p] = g_M[((size_t)p * Kk + k) * NTP + t];

    // s[a][j] = sum_i At[a][i] m[i][j]
    float s0[4], s1[4];
    #pragma unroll
    for (int j = 0; j < 4; j++) {
        s0[j] = m[j] + m[4 + j] + m[8 + j];
        s1[j] = m[4 + j] - m[8 + j] - m[12 + j];
    }
    float bv = __ldg(bias + k);
    float y00 = s0[0] + s0[1] + s0[2] + bv;
    float y01 = s0[1] - s0[2] - s0[3] + bv;
    float y10 = s1[0] + s1[1] + s1[2] + bv;
    float y11 = s1[1] - s1[2] - s1[3] + bv;

    float* op = out + (((size_t)b * Kk + k) * OH + 2u * pp) * OW + 2u * qq;
    *(float2*)op        = make_float2(y00, y01);
    *(float2*)(op + OW) = make_float2(y10, y11);
}

// ---------------------------------------------------------------------------
extern "C" void kernel_launch(void* const* d_in, const int* in_sizes, int n_in,
                              void* d_out, int out_size)
{
    const float* x    = (const float*)d_in[0];
    const float* w    = (const float*)d_in[1];
    const float* bias = (const float*)d_in[2];
    float* out        = (float*)d_out;

    filt_xform<<<(Kk * Cc) / 256, 256>>>(w);                 // 128 blocks
    in_xform<<<(Cc * NT) / 256, 256>>>(x);                   // 15376 blocks (exact)
    dim3 g3(NTP / 128, Kk / 128, 16);                        // (241, 2, 16)
    wino_gemm<<<g3, 256>>>();
    out_xform<<<(Kk * NT) / 256, 256>>>(bias, out);          // 30752 blocks (exact)
}

// round 7
// speedup vs baseline: 1.9575x; 1.9575x over previous
#include <cuda_runtime.h>
#include <stdint.h>

// ---------------------------------------------------------------------------
// Winograd F(2,3) valid conv via tf32 mma.sync (legacy tensor path; tcgen05
// is unavailable because the harness PTX targets sm_103 without 'a'):
//   1) filt_xform : U[p][c][k] = G g G^T           (tf32-rounded, k-contig)
//   2) in_xform   : V[p][c][t] = B^T d B           (tf32-rounded, t-contig)
//   3) wino_gemm  : M[p][k][t] = sum_c U*V   (mma.sync m16n8k8 tf32)
//   4) out_xform  : Y = A^T M A + bias
// ---------------------------------------------------------------------------

#define Bn 32
#define Cc 128
#define Hh 64
#define Ww 64
#define Kk 256
#define NT (Bn * 31 * 31)     /* 30752 */
#define NTP 30848             /* 241 * 128 */
#define OH 62
#define OW 62

__device__ float g_U[16 * Cc * Kk];      //   2 MB  [p][c][k]
__device__ float g_V[16 * Cc * NTP];     // 253 MB  [p][c][t]
__device__ float g_M[16 * Kk * NTP];     // 505 MB  [p][k][t]

__device__ __forceinline__ float to_tf32(float x) {
    uint32_t r;
    asm("cvt.rna.tf32.f32 %0, %1;" : "=r"(r) : "f"(x));
    return __uint_as_float(r);
}

__device__ __forceinline__ void mma_tf32(float* d, const uint32_t* a, const uint32_t* b) {
    asm volatile(
        "mma.sync.aligned.m16n8k8.row.col.f32.tf32.tf32.f32 "
        "{%0,%1,%2,%3}, {%4,%5,%6,%7}, {%8,%9}, {%0,%1,%2,%3};"
        : "+f"(d[0]), "+f"(d[1]), "+f"(d[2]), "+f"(d[3])
        : "r"(a[0]), "r"(a[1]), "r"(a[2]), "r"(a[3]), "r"(b[0]), "r"(b[1]));
}

// ---------------------------------------------------------------------------
// 1) Filter transform -> U[p][c][k] (k contiguous), tf32-rounded.
// ---------------------------------------------------------------------------
__global__ void filt_xform(const float* __restrict__ w)
{
    int idx = blockIdx.x * blockDim.x + threadIdx.x;   // 32768
    int k = idx >> 7;
    int c = idx & 127;
    const float* g = w + (size_t)(k * Cc + c) * 9;

    float w00 = g[0], w01 = g[1], w02 = g[2];
    float w10 = g[3], w11 = g[4], w12 = g[5];
    float w20 = g[6], w21 = g[7], w22 = g[8];

    float t[4][3];
    t[0][0] = w00;                      t[0][1] = w01;                      t[0][2] = w02;
    t[1][0] = 0.5f * (w00 + w10 + w20); t[1][1] = 0.5f * (w01 + w11 + w21); t[1][2] = 0.5f * (w02 + w12 + w22);
    t[2][0] = 0.5f * (w00 - w10 + w20); t[2][1] = 0.5f * (w01 - w11 + w21); t[2][2] = 0.5f * (w02 - w12 + w22);
    t[3][0] = w20;                      t[3][1] = w21;                      t[3][2] = w22;

    #pragma unroll
    for (int a = 0; a < 4; a++) {
        float u0 = t[a][0];
        float u1 = 0.5f * (t[a][0] + t[a][1] + t[a][2]);
        float u2 = 0.5f * (t[a][0] - t[a][1] + t[a][2]);
        float u3 = t[a][2];
        g_U[((size_t)(a * 4 + 0) * Cc + c) * Kk + k] = to_tf32(u0);
        g_U[((size_t)(a * 4 + 1) * Cc + c) * Kk + k] = to_tf32(u1);
        g_U[((size_t)(a * 4 + 2) * Cc + c) * Kk + k] = to_tf32(u2);
        g_U[((size_t)(a * 4 + 3) * Cc + c) * Kk + k] = to_tf32(u3);
    }
}

// ---------------------------------------------------------------------------
// 2) Input transform -> V[p][c][t] (t contiguous), tf32-rounded.
// ---------------------------------------------------------------------------
__global__ void in_xform(const float* __restrict__ x)
{
    unsigned idx = blockIdx.x * blockDim.x + threadIdx.x;   // < Cc*NT exact
    unsigned c = idx / NT;
    unsigned t = idx - c * NT;
    unsigned b  = t / 961u;
    unsigned r  = t - b * 961u;
    unsigned pp = r / 31u;
    unsigned qq = r - pp * 31u;

    const float* xp = x + (((size_t)(b * Cc + c) * Hh + 2u * pp) * Ww + 2u * qq);

    float d[4][4];
    #pragma unroll
    for (int i = 0; i < 4; i++)
        #pragma unroll
        for (int j = 0; j < 4; j++)
            d[i][j] = xp[i * Ww + j];

    float tm[4][4];
    #pragma unroll
    for (int j = 0; j < 4; j++) {
        tm[0][j] = d[0][j] - d[2][j];
        tm[1][j] = d[1][j] + d[2][j];
        tm[2][j] = d[2][j] - d[1][j];
        tm[3][j] = d[1][j] - d[3][j];
    }

    #pragma unroll
    for (int a = 0; a < 4; a++) {
        float v0 = tm[a][0] - tm[a][2];
        float v1 = tm[a][1] + tm[a][2];
        float v2 = tm[a][2] - tm[a][1];
        float v3 = tm[a][1] - tm[a][3];
        g_V[((size_t)(a * 4 + 0) * Cc + c) * NTP + t] = to_tf32(v0);
        g_V[((size_t)(a * 4 + 1) * Cc + c) * NTP + t] = to_tf32(v1);
        g_V[((size_t)(a * 4 + 2) * Cc + c) * NTP + t] = to_tf32(v2);
        g_V[((size_t)(a * 4 + 3) * Cc + c) * NTP + t] = to_tf32(v3);
    }
}

// ---------------------------------------------------------------------------
// 3) tf32 tensor GEMM:  M[k][t] = sum_c U[c][k] * V[c][t], per point p.
//    CTA tile 128k x 128t, 256 thr (8 warps: wk=wid&3 -> 32k, wt=wid>>2 -> 64t)
//    K-chunks of 8 c, double-buffered smem (pitch 136 -> conflict-free frags).
//    grid = (241, 2, 16)
// ---------------------------------------------------------------------------
#define PITCH 136

__global__ void __launch_bounds__(256, 2) wino_gemm()
{
    __shared__ float Us[2][8][PITCH];   // [buf][c][k]
    __shared__ float Vs[2][8][PITCH];   // [buf][c][t]

    const int p  = blockIdx.z;
    const int kb = blockIdx.y;
    const int tb = blockIdx.x;

    const int tid = threadIdx.x;
    const int wid = tid >> 5, lane = tid & 31;
    const int g   = lane >> 2, tig = lane & 3;
    const int wk  = (wid & 3) * 32;          // warp k origin in CTA
    const int wt  = (wid >> 2) * 64;         // warp t origin in CTA

    const int uc  = tid >> 5;                // staging: c row
    const int u4  = (tid & 31) * 4;          // staging: 4-float offset

    const float* Uptr = g_U + ((size_t)p * Cc + uc) * Kk + kb * 128 + u4;
    const float* Vptr = g_V + ((size_t)p * Cc + uc) * NTP + (size_t)tb * 128 + u4;

    float acc[2][8][4];
    #pragma unroll
    for (int mi = 0; mi < 2; mi++)
        #pragma unroll
        for (int nj = 0; nj < 8; nj++)
            #pragma unroll
            for (int q = 0; q < 4; q++)
                acc[mi][nj][q] = 0.0f;

    // preload chunk 0
    {
        float4 ur = *(const float4*)Uptr;
        float4 vr = *(const float4*)Vptr;
        *(float4*)&Us[0][uc][u4] = ur;
        *(float4*)&Vs[0][uc][u4] = vr;
    }
    __syncthreads();

    int cur = 0;
    #pragma unroll 1
    for (int it = 0; it < 16; it++) {
        float4 ur, vr;
        if (it < 15) {
            ur = *(const float4*)(Uptr + (size_t)(it + 1) * 8 * Kk);
            vr = *(const float4*)(Vptr + (size_t)(it + 1) * 8 * NTP);
        }

        // A fragments (M=k rows, K=c cols): a0=(g,tig) a1=(g+8,tig) a2=(g,tig+4) a3=(g+8,tig+4)
        uint32_t a[2][4];
        #pragma unroll
        for (int mi = 0; mi < 2; mi++) {
            int km = wk + mi * 16;
            a[mi][0] = __float_as_uint(Us[cur][tig]    [km + g]);
            a[mi][1] = __float_as_uint(Us[cur][tig]    [km + g + 8]);
            a[mi][2] = __float_as_uint(Us[cur][tig + 4][km + g]);
            a[mi][3] = __float_as_uint(Us[cur][tig + 4][km + g + 8]);
        }
        #pragma unroll
        for (int nj = 0; nj < 8; nj++) {
            int tn = wt + nj * 8;
            uint32_t b[2];
            b[0] = __float_as_uint(Vs[cur][tig]    [tn + g]);
            b[1] = __float_as_uint(Vs[cur][tig + 4][tn + g]);
            mma_tf32(acc[0][nj], a[0], b);
            mma_tf32(acc[1][nj], a[1], b);
        }

        __syncthreads();
        if (it < 15) {
            *(float4*)&Us[cur ^ 1][uc][u4] = ur;
            *(float4*)&Vs[cur ^ 1][uc][u4] = vr;
            __syncthreads();
            cur ^= 1;
        }
    }

    // epilogue: D frag (g, 2tig) (g,2tig+1) (g+8,2tig) (g+8,2tig+1)
    float* Mp = g_M + ((size_t)p * Kk + kb * 128 + wk) * NTP + (size_t)tb * 128 + wt;
    #pragma unroll
    for (int mi = 0; mi < 2; mi++) {
        #pragma unroll
        for (int nj = 0; nj < 8; nj++) {
            int t_off = nj * 8 + 2 * tig;
            float* r0 = Mp + (size_t)(mi * 16 + g) * NTP + t_off;
            *(float2*)r0                       = make_float2(acc[mi][nj][0], acc[mi][nj][1]);
            *(float2*)(r0 + (size_t)8 * NTP)   = make_float2(acc[mi][nj][2], acc[mi][nj][3]);
        }
    }
}

// ---------------------------------------------------------------------------
// 4) Inverse transform + bias (DRAM-roofline already)
// ---------------------------------------------------------------------------
__global__ void out_xform(const float* __restrict__ bias, float* __restrict__ out)
{
    unsigned idx = blockIdx.x * blockDim.x + threadIdx.x;   // < Kk*NT exact
    unsigned k = idx / NT;
    unsigned t = idx - k * NT;
    unsigned b  = t / 961u;
    unsigned r  = t - b * 961u;
    unsigned pp = r / 31u;
    unsigned qq = r - pp * 31u;

    float m[16];
    #pragma unroll
    for (int p = 0; p < 16; p++)
        m[p] = g_M[((size_t)p * Kk + k) * NTP + t];

    float s0[4], s1[4];
    #pragma unroll
    for (int j = 0; j < 4; j++) {
        s0[j] = m[j] + m[4 + j] + m[8 + j];
        s1[j] = m[4 + j] - m[8 + j] - m[12 + j];
    }
    float bv = __ldg(bias + k);
    float y00 = s0[0] + s0[1] + s0[2] + bv;
    float y01 = s0[1] - s0[2] - s0[3] + bv;
    float y10 = s1[0] + s1[1] + s1[2] + bv;
    float y11 = s1[1] - s1[2] - s1[3] + bv;

    float* op = out + (((size_t)b * Kk + k) * OH + 2u * pp) * OW + 2u * qq;
    *(float2*)op        = make_float2(y00, y01);
    *(float2*)(op + OW) = make_float2(y10, y11);
}

// ---------------------------------------------------------------------------
extern "C" void kernel_launch(void* const* d_in, const int* in_sizes, int n_in,
                              void* d_out, int out_size)
{
    const float* x    = (const float*)d_in[0];
    const float* w    = (const float*)d_in[1];
    const float* bias = (const float*)d_in[2];
    float* out        = (float*)d_out;

    filt_xform<<<(Kk * Cc) / 256, 256>>>(w);
    in_xform<<<(Cc * NT) / 256, 256>>>(x);
    dim3 g3(NTP / 128, Kk / 128, 16);                 // (241, 2, 16)
    wino_gemm<<<g3, 256>>>();
    out_xform<<<(Kk * NT) / 256, 256>>>(bias, out);
}